// round 14
// baseline (speedup 1.0000x reference)
#include <cuda_runtime.h>
#include <cuda_bf16.h>
#include <cuda_fp16.h>
#include <math.h>
#include <stdint.h>
#include <string.h>

// Problem constants
#define SEQ    128
#define BATCH  32
#define NTOKEN 32000
#define NINP   1024
#define NHID   1024
#define MROWS  (SEQ * BATCH)          // 4096

// ---------------- scratch (no runtime allocation allowed) ----------------
__device__ float  g_xin[MROWS * NHID];        // 16 MB
__device__ float  g_hs [MROWS * NHID];        // 16 MB (fp32, scan-internal)
__device__ __half g_h16buf[MROWS * NHID];     // 8 MB (fp16: emb16 then hs16)
__device__ __half g_decW_h[NTOKEN * NHID];    // 64 MB (fp16)
__device__ __half g_wih_h[NHID * NINP];       // 2 MB (fp16)
__device__ unsigned g_arr[16 * 32];           // 4 groups x 4 sub-counters, 128B apart

// ---------------- helpers ----------------
__device__ __forceinline__ uint32_t smem_u32(const void* p) {
    return (uint32_t)__cvta_generic_to_shared(p);
}

#define LDSM_X4(r0, r1, r2, r3, addr) \
    asm volatile("ldmatrix.sync.aligned.m8n8.x4.shared.b16 {%0,%1,%2,%3}, [%4];" \
        : "=r"(r0), "=r"(r1), "=r"(r2), "=r"(r3) : "r"(addr))

#define FMA_X2(acc, a, b) \
    asm volatile("fma.rn.f32x2 %0, %1, %2, %0;" : "+l"(acc) : "l"(a), "l"(b))

// =============== prep_a: dec_W -> fp16 (the big conversion) =============
__global__ __launch_bounds__(256)
void prep_a_kernel(const float* __restrict__ dec_W)
{
    const long n4 = (long)NTOKEN * NHID / 4;
    long i = (long)blockIdx.x * 256 + threadIdx.x;
    const long stride = (long)gridDim.x * 256;
    for (; i < n4; i += stride) {
        float4 v = ((const float4*)dec_W)[i];
        __half2 h0 = __floats2half2_rn(v.x, v.y);
        __half2 h1 = __floats2half2_rn(v.z, v.w);
        uint2 o = { *(uint32_t*)&h0, *(uint32_t*)&h1 };
        ((uint2*)g_decW_h)[i] = o;
    }
}

// =============== prep_b: W_ih cvt + emb gather + counter reset =============
#define PREP_B_BLOCKS 192

__global__ __launch_bounds__(256)
void prep_b_kernel(const float* __restrict__ W_ih,
                   const float* __restrict__ emb_W,
                   const int*   __restrict__ input)
{
    const int bid = blockIdx.x;
    const int t   = threadIdx.x;
    if (bid == 0 && t < 256) { g_arr[t] = 0u; g_arr[t + 256] = 0u; }

    if (bid < 64) {
        const long n4 = (long)NHID * NINP / 4;
        long i = (long)bid * 256 + t;
        const long stride = 64L * 256;
        for (; i < n4; i += stride) {
            float4 v = ((const float4*)W_ih)[i];
            __half2 h0 = __floats2half2_rn(v.x, v.y);
            __half2 h1 = __floats2half2_rn(v.z, v.w);
            uint2 o = { *(uint32_t*)&h0, *(uint32_t*)&h1 };
            ((uint2*)g_wih_h)[i] = o;
        }
    } else {
        const long n4 = (long)MROWS * NINP / 4;
        long i = (long)(bid - 64) * 256 + t;
        const long stride = 128L * 256;
        for (; i < n4; i += stride) {
            int row = (int)(i >> 8);          // NINP/4 = 256 float4 per row
            int c4  = (int)(i & 255);
            int tok = input[row];
            float4 v = *(const float4*)(emb_W + (long)tok * NINP + c4 * 4);
            __half2 h0 = __floats2half2_rn(v.x, v.y);
            __half2 h1 = __floats2half2_rn(v.z, v.w);
            uint2 o = { *(uint32_t*)&h0, *(uint32_t*)&h1 };
            *(uint2*)(g_h16buf + (long)row * NINP + c4 * 4) = o;
        }
    }
}

// ============ fp16 mma.sync GEMM with ldmatrix fragments (R13) ============
#define DBM 128
#define DBN 128
#define DBK 64                   // halves per tile row = 128 bytes
#define NSTG 3
#define NTHR 128
#define A_ST (DBM * 128)         // 16 KB
#define B_ST (DBN * 128)         // 16 KB
#define DEC_SMEM (NSTG * (A_ST + B_ST))   // 96 KB

__global__ __launch_bounds__(NTHR, 2)
void gemm_f16_ldsm(const __half* __restrict__ A,
                   const __half* __restrict__ B,
                   const float*  __restrict__ bias,
                   float*        __restrict__ C,
                   int M, int N, int K)
{
    extern __shared__ __align__(1024) char smem[];
    const uint32_t sA = smem_u32(smem);
    const uint32_t sB = sA + NSTG * A_ST;

    const int t    = threadIdx.x;
    const int warp = t >> 5;
    const int lane = t & 31;
    const int m0   = blockIdx.x * DBM;
    const int n0   = blockIdx.y * DBN;
    const int wm   = warp & 1;
    const int wn   = warp >> 1;
    const int g    = lane >> 2;
    const int tg   = lane & 3;

    const int mat = lane >> 3;
    const int sub = lane & 7;

    uint32_t aRowOff[4], aSw[4];
#pragma unroll
    for (int mi = 0; mi < 4; ++mi) {
        int r = wm * 64 + mi * 16 + (mat & 1) * 8 + sub;
        aRowOff[mi] = (uint32_t)(r * 128);
        aSw[mi]     = (uint32_t)(r & 7);
    }
    const uint32_t aMatK = (uint32_t)(mat >> 1);

    uint32_t bRowOff[4], bSw[4];
#pragma unroll
    for (int p = 0; p < 4; ++p) {
        int r = wn * 64 + (p * 2 + (mat >> 1)) * 8 + sub;
        bRowOff[p] = (uint32_t)(r * 128);
        bSw[p]     = (uint32_t)(r & 7);
    }
    const uint32_t bMatK = (uint32_t)(mat & 1);

    float acc[4][8][4];
#pragma unroll
    for (int mi = 0; mi < 4; ++mi)
#pragma unroll
        for (int ni = 0; ni < 8; ++ni)
#pragma unroll
            for (int r = 0; r < 4; ++r) acc[mi][ni][r] = 0.0f;

    auto load_chunk = [&](int c) {
        const int s  = c % NSTG;
        const int k0 = c * DBK;
#pragma unroll
        for (int i = 0; i < 8; ++i) {
            int id  = t + i * NTHR;
            int row = id >> 3;
            int kc  = id & 7;
            uint32_t sw = (uint32_t)(row * 128 + ((kc ^ (row & 7)) << 4));
            uint32_t dst = sA + s * A_ST + sw;
            const __half* ga = A + (long)(m0 + row) * K + k0 + kc * 8;
            asm volatile("cp.async.cg.shared.global [%0], [%1], 16;" :: "r"(dst), "l"(ga));
        }
#pragma unroll
        for (int i = 0; i < 8; ++i) {
            int id  = t + i * NTHR;
            int row = id >> 3;
            int kc  = id & 7;
            uint32_t sw = (uint32_t)(row * 128 + ((kc ^ (row & 7)) << 4));
            uint32_t dst = sB + s * B_ST + sw;
            const __half* gb = B + (long)(n0 + row) * K + k0 + kc * 8;
            asm volatile("cp.async.cg.shared.global [%0], [%1], 16;" :: "r"(dst), "l"(gb));
        }
        asm volatile("cp.async.commit_group;");
    };

    const int NCHUNK = K / DBK;   // 16
    load_chunk(0);
    load_chunk(1);

    for (int c = 0; c < NCHUNK; ++c) {
        const int buf = c % NSTG;
        asm volatile("cp.async.wait_group 1;");
        __syncthreads();

        if (c + 2 < NCHUNK) {
            load_chunk(c + 2);
        } else {
            asm volatile("cp.async.commit_group;");
        }

        const uint32_t Ab = sA + buf * A_ST;
        const uint32_t Bb = sB + buf * B_ST;

#pragma unroll
        for (int kk = 0; kk < 4; ++kk) {     // k16 per iter
            uint32_t a[4][4];
            uint32_t b[8][2];
            const uint32_t cA = (uint32_t)(kk * 2) + aMatK;
            const uint32_t cB = (uint32_t)(kk * 2) + bMatK;
#pragma unroll
            for (int mi = 0; mi < 4; ++mi) {
                uint32_t addr = Ab + aRowOff[mi] + (((cA ^ aSw[mi])) << 4);
                LDSM_X4(a[mi][0], a[mi][1], a[mi][2], a[mi][3], addr);
            }
#pragma unroll
            for (int p = 0; p < 4; ++p) {
                uint32_t addr = Bb + bRowOff[p] + (((cB ^ bSw[p])) << 4);
                uint32_t r0, r1, r2, r3;
                LDSM_X4(r0, r1, r2, r3, addr);
                b[2 * p][0] = r0;     b[2 * p][1] = r1;
                b[2 * p + 1][0] = r2; b[2 * p + 1][1] = r3;
            }
#pragma unroll
            for (int mi = 0; mi < 4; ++mi)
#pragma unroll
                for (int ni = 0; ni < 8; ++ni) {
                    asm volatile(
                        "mma.sync.aligned.m16n8k16.row.col.f32.f16.f16.f32 "
                        "{%0,%1,%2,%3}, {%4,%5,%6,%7}, {%8,%9}, {%0,%1,%2,%3};\n"
                        : "+f"(acc[mi][ni][0]), "+f"(acc[mi][ni][1]),
                          "+f"(acc[mi][ni][2]), "+f"(acc[mi][ni][3])
                        : "r"(a[mi][0]), "r"(a[mi][1]), "r"(a[mi][2]), "r"(a[mi][3]),
                          "r"(b[ni][0]), "r"(b[ni][1]));
                }
        }
    }

    // ---- epilogue: add bias, store ----
#pragma unroll
    for (int mi = 0; mi < 4; ++mi) {
        int rbase = m0 + wm * 64 + mi * 16 + g;
#pragma unroll
        for (int ni = 0; ni < 8; ++ni) {
            int cc = n0 + wn * 64 + ni * 8 + 2 * tg;
            float b0 = bias[cc], b1 = bias[cc + 1];
            float2 v0 = make_float2(acc[mi][ni][0] + b0, acc[mi][ni][1] + b1);
            float2 v1 = make_float2(acc[mi][ni][2] + b0, acc[mi][ni][3] + b1);
            *(float2*)(C + (long)rbase * N + cc)       = v0;
            *(float2*)(C + (long)(rbase + 8) * N + cc) = v1;
        }
    }
}

// ---------------- persistent RNN scan: 4 independent sync groups -----------
// 256 CTAs x 256 threads, 2 CTAs/SM. Group bg = cb>>6 owns 8 batches; groups
// sync only among their own 64 CTAs. Same-SM wave pairs are cross-group; a
// one-time half-step stagger for groups 2,3 de-phases the pairs so one CTA
// computes while the other waits (without it the groups are phase-locked and
// the overlap never materializes). Arrivals spread over 4 line-separated
// sub-counters per group (16 serialized atomics each instead of 64).
#define SCAN_NB   256
#define SCAN_THR  256
#define SCAN_GRP  64
#define HS_PAD    1032

__device__ __forceinline__ void group_barrier(int bg, int sc, unsigned gen, int t) {
    __syncthreads();   // all global writes of this CTA issued
    if (t == 0) {
        asm volatile("red.release.gpu.global.add.u32 [%0], %1;"
                     :: "l"(&g_arr[(bg * 4 + sc) * 32]), "r"(1u) : "memory");
        unsigned target = gen * (unsigned)SCAN_GRP;
        unsigned sum;
        do {
            unsigned v0, v1, v2, v3;
            asm volatile("ld.acquire.gpu.global.u32 %0, [%1];"
                         : "=r"(v0) : "l"(&g_arr[(bg * 4 + 0) * 32]) : "memory");
            asm volatile("ld.acquire.gpu.global.u32 %0, [%1];"
                         : "=r"(v1) : "l"(&g_arr[(bg * 4 + 1) * 32]) : "memory");
            asm volatile("ld.acquire.gpu.global.u32 %0, [%1];"
                         : "=r"(v2) : "l"(&g_arr[(bg * 4 + 2) * 32]) : "memory");
            asm volatile("ld.acquire.gpu.global.u32 %0, [%1];"
                         : "=r"(v3) : "l"(&g_arr[(bg * 4 + 3) * 32]) : "memory");
            sum = v0 + v1 + v2 + v3;
        } while (sum < target);
    }
    __syncthreads();   // propagate acquired visibility CTA-wide
}

__global__ __launch_bounds__(SCAN_THR, 2)
void scan_kernel(const float* __restrict__ xin,
                 const float* __restrict__ h0,
                 const float* __restrict__ W_hh,
                 const float* __restrict__ b_hh,
                 const float* __restrict__ alpha,
                 float*       __restrict__ hs,
                 __half*      __restrict__ hs16,
                 float*       __restrict__ hidden_f)
{
    extern __shared__ float sm[];
    float* hsh  = sm;                      // 8 * HS_PAD
    float* red  = sm + 8 * HS_PAD;         // 2048
    float* alph = red + 2048;              // 128

    const int t  = threadIdx.x;
    const int cb = blockIdx.x;
    const int bg = cb >> 6;
    const int jg = cb & 63;
    const int sc = jg & 3;         // arrival sub-counter
    const int j0 = jg * 16;
    const int b0 = bg * 8;

    const int jj = t & 15;
    const int kg = t >> 4;

    if (t < 128) alph[t] = alpha[t];

    unsigned long long wf[32];
    {
        const float* wrow = W_hh + (long)(j0 + jj) * NHID + kg * 64;
#pragma unroll
        for (int q = 0; q < 16; ++q) {
            ulonglong2 w = *(const ulonglong2*)(wrow + q * 4);
            wf[2 * q]     = w.x;
            wf[2 * q + 1] = w.y;
        }
    }

    const int rb  = t >> 4;
    const int rjj = t & 15;
    const float bh = b_hh[j0 + rjj];

    // one-time half-step stagger for groups 2,3: de-phases the co-resident
    // cross-group CTA pairs so compute and barrier-wait phases interleave.
    if (bg >= 2 && t == 0) {
        long long start = clock64();
        while (clock64() - start < 3500) { }
    }
    __syncthreads();

    for (int s = 0; s < SEQ; ++s) {
        const float* hprev = (s == 0) ? (h0 + (long)b0 * NHID)
                                      : (hs + ((long)(s - 1) * BATCH + b0) * NHID);

        float xv = 0.0f;
        long widx = 0;
        if (t < 128) {
            widx = ((long)s * BATCH + b0 + rb) * NHID + j0 + rjj;
            xv = xin[widx];
        }

#pragma unroll
        for (int i = 0; i < 8; ++i) {
            int idx = t + i * SCAN_THR;
            int row = idx >> 8;
            int c4  = idx & 255;
            float4 v = *(const float4*)(hprev + (long)row * NHID + c4 * 4);
            *(float4*)&hsh[row * HS_PAD + c4 * 4] = v;
        }
        __syncthreads();

#pragma unroll
        for (int b = 0; b < 8; ++b) {
            const float* hb = &hsh[b * HS_PAD + kg * 64];
            unsigned long long a0 = 0ull, a1 = 0ull;
#pragma unroll
            for (int q = 0; q < 16; ++q) {
                ulonglong2 hq = *(const ulonglong2*)(hb + q * 4);
                FMA_X2(a0, hq.x, wf[2 * q]);
                FMA_X2(a1, hq.y, wf[2 * q + 1]);
            }
            float2 f0, f1;
            memcpy(&f0, &a0, 8);
            memcpy(&f1, &a1, 8);
            red[(kg * 8 + b) * 16 + jj] = (f0.x + f0.y) + (f1.x + f1.y);
        }
        __syncthreads();

        if (t < 128) {
            float sum = 0.0f;
#pragma unroll
            for (int kk = 0; kk < 16; ++kk) sum += red[(kk * 8 + rb) * 16 + rjj];
            float val = xv + sum + bh;
            float hnew = alph[s] * tanhf(val);
            hs[widx] = hnew;
            hs16[widx] = __float2half_rn(hnew);
            if (s == SEQ - 1) hidden_f[(long)(b0 + rb) * NHID + j0 + rjj] = hnew;
        }

        if (s < SEQ - 1) group_barrier(bg, sc, (unsigned)(s + 1), t);
    }
}

// ---------------- launch ----------------
extern "C" void kernel_launch(void* const* d_in, const int* in_sizes, int n_in,
                              void* d_out, int out_size)
{
    const int*   input  = (const int*)  d_in[0];
    const float* hidden = (const float*)d_in[1];
    const float* emb_W  = (const float*)d_in[2];
    const float* W_ih   = (const float*)d_in[3];
    const float* W_hh   = (const float*)d_in[4];
    const float* b_ih   = (const float*)d_in[5];
    const float* b_hh   = (const float*)d_in[6];
    const float* alpha  = (const float*)d_in[7];
    const float* dec_W  = (const float*)d_in[8];
    const float* dec_b  = (const float*)d_in[9];

    float* decoded  = (float*)d_out;                          // [S,B,NTOKEN]
    float* hidden_f = (float*)d_out + (long)MROWS * NTOKEN;   // [B,NHID]

    void *xin_p, *hs_p, *h16_p, *decwh_p, *wihh_p;
    cudaGetSymbolAddress(&xin_p,   g_xin);
    cudaGetSymbolAddress(&hs_p,    g_hs);
    cudaGetSymbolAddress(&h16_p,   g_h16buf);
    cudaGetSymbolAddress(&decwh_p, g_decW_h);
    cudaGetSymbolAddress(&wihh_p,  g_wih_h);
    float*  xin    = (float*)xin_p;
    float*  hs     = (float*)hs_p;
    __half* h16    = (__half*)h16_p;    // emb16 first, hs16 later
    __half* decwh  = (__half*)decwh_p;
    __half* wihh   = (__half*)wihh_p;

    const int scan_smem = (8 * HS_PAD + 2048 + 128) * (int)sizeof(float);
    cudaFuncSetAttribute(scan_kernel, cudaFuncAttributeMaxDynamicSharedMemorySize, scan_smem);
    cudaFuncSetAttribute(gemm_f16_ldsm, cudaFuncAttributeMaxDynamicSharedMemorySize, DEC_SMEM);

    // 1) prep_a: dec_W -> fp16
    prep_a_kernel<<<2048, 256>>>(dec_W);

    // 2) prep_b: W_ih cvt + emb gather (fp16) + counter reset
    prep_b_kernel<<<PREP_B_BLOCKS, 256>>>(W_ih, emb_W, input);

    // 3) xin = emb @ W_ih^T + b_ih on fp16 tensor cores [4096 x 1024]
    gemm_f16_ldsm<<<dim3(MROWS / DBM, NHID / DBN), NTHR, DEC_SMEM>>>(
        h16, wihh, b_ih, xin, MROWS, NHID, NINP);

    // 4) recurrence — 4th launch: ncu target
    scan_kernel<<<SCAN_NB, SCAN_THR, scan_smem>>>(xin, hidden, W_hh, b_hh, alpha,
                                                  hs, h16, hidden_f);

    // 5) decoder: decoded = hs @ dec_W^T + dec_b  [4096 x 32000]
    gemm_f16_ldsm<<<dim3(MROWS / DBM, NTOKEN / DBN), NTHR, DEC_SMEM>>>(
        h16, decwh, dec_b, decoded, MROWS, NTOKEN, NHID);
}

// round 15
// speedup vs baseline: 1.0920x; 1.0920x over previous
#include <cuda_runtime.h>
#include <cuda_bf16.h>
#include <cuda_fp16.h>
#include <math.h>
#include <stdint.h>
#include <string.h>

// Problem constants
#define SEQ    128
#define BATCH  32
#define NTOKEN 32000
#define NINP   1024
#define NHID   1024
#define MROWS  (SEQ * BATCH)          // 4096

// ---------------- scratch (no runtime allocation allowed) ----------------
__device__ float  g_xin[MROWS * NHID];        // 16 MB
__device__ float  g_hs [MROWS * NHID];        // 16 MB (fp32, scan-internal)
__device__ __half g_h16buf[MROWS * NHID];     // 8 MB (fp16: emb16 then hs16)
__device__ __half g_decW_h[NTOKEN * NHID];    // 64 MB (fp16)
__device__ __half g_wih_h[NHID * NINP];       // 2 MB (fp16)
__device__ unsigned g_arr[8 * 32];            // group counters, 128B apart

// ---------------- helpers ----------------
__device__ __forceinline__ uint32_t smem_u32(const void* p) {
    return (uint32_t)__cvta_generic_to_shared(p);
}

#define LDSM_X4(r0, r1, r2, r3, addr) \
    asm volatile("ldmatrix.sync.aligned.m8n8.x4.shared.b16 {%0,%1,%2,%3}, [%4];" \
        : "=r"(r0), "=r"(r1), "=r"(r2), "=r"(r3) : "r"(addr))

#define FMA_X2(acc, a, b) \
    asm volatile("fma.rn.f32x2 %0, %1, %2, %0;" : "+l"(acc) : "l"(a), "l"(b))

// =============== prep_b: W_ih cvt + emb gather + counter reset =============
#define PREP_B_BLOCKS 192

__global__ __launch_bounds__(256)
void prep_b_kernel(const float* __restrict__ W_ih,
                   const float* __restrict__ emb_W,
                   const int*   __restrict__ input)
{
    const int bid = blockIdx.x;
    const int t   = threadIdx.x;
    if (bid == 0 && t < 256) g_arr[t] = 0u;

    if (bid < 64) {
        const long n4 = (long)NHID * NINP / 4;
        long i = (long)bid * 256 + t;
        const long stride = 64L * 256;
        for (; i < n4; i += stride) {
            float4 v = ((const float4*)W_ih)[i];
            __half2 h0 = __floats2half2_rn(v.x, v.y);
            __half2 h1 = __floats2half2_rn(v.z, v.w);
            uint2 o = { *(uint32_t*)&h0, *(uint32_t*)&h1 };
            ((uint2*)g_wih_h)[i] = o;
        }
    } else {
        const long n4 = (long)MROWS * NINP / 4;
        long i = (long)(bid - 64) * 256 + t;
        const long stride = 128L * 256;
        for (; i < n4; i += stride) {
            int row = (int)(i >> 8);          // NINP/4 = 256 float4 per row
            int c4  = (int)(i & 255);
            int tok = input[row];
            float4 v = *(const float4*)(emb_W + (long)tok * NINP + c4 * 4);
            __half2 h0 = __floats2half2_rn(v.x, v.y);
            __half2 h1 = __floats2half2_rn(v.z, v.w);
            uint2 o = { *(uint32_t*)&h0, *(uint32_t*)&h1 };
            *(uint2*)(g_h16buf + (long)row * NINP + c4 * 4) = o;
        }
    }
}

// ============ fp16 mma.sync GEMM with ldmatrix fragments (R13) ============
#define DBM 128
#define DBN 128
#define DBK 64                   // halves per tile row = 128 bytes
#define NSTG 3
#define NTHR 128
#define A_ST (DBM * 128)         // 16 KB
#define B_ST (DBN * 128)         // 16 KB
#define DEC_SMEM (NSTG * (A_ST + B_ST))   // 96 KB

__global__ __launch_bounds__(NTHR, 2)
void gemm_f16_ldsm(const __half* __restrict__ A,
                   const __half* __restrict__ B,
                   const float*  __restrict__ bias,
                   float*        __restrict__ C,
                   int M, int N, int K)
{
    extern __shared__ __align__(1024) char smem[];
    const uint32_t sA = smem_u32(smem);
    const uint32_t sB = sA + NSTG * A_ST;

    const int t    = threadIdx.x;
    const int warp = t >> 5;
    const int lane = t & 31;
    const int m0   = blockIdx.x * DBM;
    const int n0   = blockIdx.y * DBN;
    const int wm   = warp & 1;
    const int wn   = warp >> 1;
    const int g    = lane >> 2;
    const int tg   = lane & 3;

    const int mat = lane >> 3;
    const int sub = lane & 7;

    uint32_t aRowOff[4], aSw[4];
#pragma unroll
    for (int mi = 0; mi < 4; ++mi) {
        int r = wm * 64 + mi * 16 + (mat & 1) * 8 + sub;
        aRowOff[mi] = (uint32_t)(r * 128);
        aSw[mi]     = (uint32_t)(r & 7);
    }
    const uint32_t aMatK = (uint32_t)(mat >> 1);

    uint32_t bRowOff[4], bSw[4];
#pragma unroll
    for (int p = 0; p < 4; ++p) {
        int r = wn * 64 + (p * 2 + (mat >> 1)) * 8 + sub;
        bRowOff[p] = (uint32_t)(r * 128);
        bSw[p]     = (uint32_t)(r & 7);
    }
    const uint32_t bMatK = (uint32_t)(mat & 1);

    float acc[4][8][4];
#pragma unroll
    for (int mi = 0; mi < 4; ++mi)
#pragma unroll
        for (int ni = 0; ni < 8; ++ni)
#pragma unroll
            for (int r = 0; r < 4; ++r) acc[mi][ni][r] = 0.0f;

    auto load_chunk = [&](int c) {
        const int s  = c % NSTG;
        const int k0 = c * DBK;
#pragma unroll
        for (int i = 0; i < 8; ++i) {
            int id  = t + i * NTHR;
            int row = id >> 3;
            int kc  = id & 7;
            uint32_t sw = (uint32_t)(row * 128 + ((kc ^ (row & 7)) << 4));
            uint32_t dst = sA + s * A_ST + sw;
            const __half* ga = A + (long)(m0 + row) * K + k0 + kc * 8;
            asm volatile("cp.async.cg.shared.global [%0], [%1], 16;" :: "r"(dst), "l"(ga));
        }
#pragma unroll
        for (int i = 0; i < 8; ++i) {
            int id  = t + i * NTHR;
            int row = id >> 3;
            int kc  = id & 7;
            uint32_t sw = (uint32_t)(row * 128 + ((kc ^ (row & 7)) << 4));
            uint32_t dst = sB + s * B_ST + sw;
            const __half* gb = B + (long)(n0 + row) * K + k0 + kc * 8;
            asm volatile("cp.async.cg.shared.global [%0], [%1], 16;" :: "r"(dst), "l"(gb));
        }
        asm volatile("cp.async.commit_group;");
    };

    const int NCHUNK = K / DBK;   // 16
    load_chunk(0);
    load_chunk(1);

    for (int c = 0; c < NCHUNK; ++c) {
        const int buf = c % NSTG;
        asm volatile("cp.async.wait_group 1;");
        __syncthreads();

        if (c + 2 < NCHUNK) {
            load_chunk(c + 2);
        } else {
            asm volatile("cp.async.commit_group;");
        }

        const uint32_t Ab = sA + buf * A_ST;
        const uint32_t Bb = sB + buf * B_ST;

#pragma unroll
        for (int kk = 0; kk < 4; ++kk) {     // k16 per iter
            uint32_t a[4][4];
            uint32_t b[8][2];
            const uint32_t cA = (uint32_t)(kk * 2) + aMatK;
            const uint32_t cB = (uint32_t)(kk * 2) + bMatK;
#pragma unroll
            for (int mi = 0; mi < 4; ++mi) {
                uint32_t addr = Ab + aRowOff[mi] + (((cA ^ aSw[mi])) << 4);
                LDSM_X4(a[mi][0], a[mi][1], a[mi][2], a[mi][3], addr);
            }
#pragma unroll
            for (int p = 0; p < 4; ++p) {
                uint32_t addr = Bb + bRowOff[p] + (((cB ^ bSw[p])) << 4);
                uint32_t r0, r1, r2, r3;
                LDSM_X4(r0, r1, r2, r3, addr);
                b[2 * p][0] = r0;     b[2 * p][1] = r1;
                b[2 * p + 1][0] = r2; b[2 * p + 1][1] = r3;
            }
#pragma unroll
            for (int mi = 0; mi < 4; ++mi)
#pragma unroll
                for (int ni = 0; ni < 8; ++ni) {
                    asm volatile(
                        "mma.sync.aligned.m16n8k16.row.col.f32.f16.f16.f32 "
                        "{%0,%1,%2,%3}, {%4,%5,%6,%7}, {%8,%9}, {%0,%1,%2,%3};\n"
                        : "+f"(acc[mi][ni][0]), "+f"(acc[mi][ni][1]),
                          "+f"(acc[mi][ni][2]), "+f"(acc[mi][ni][3])
                        : "r"(a[mi][0]), "r"(a[mi][1]), "r"(a[mi][2]), "r"(a[mi][3]),
                          "r"(b[ni][0]), "r"(b[ni][1]));
                }
        }
    }

    // ---- epilogue: add bias, store ----
#pragma unroll
    for (int mi = 0; mi < 4; ++mi) {
        int rbase = m0 + wm * 64 + mi * 16 + g;
#pragma unroll
        for (int ni = 0; ni < 8; ++ni) {
            int cc = n0 + wn * 64 + ni * 8 + 2 * tg;
            float b0 = bias[cc], b1 = bias[cc + 1];
            float2 v0 = make_float2(acc[mi][ni][0] + b0, acc[mi][ni][1] + b1);
            float2 v1 = make_float2(acc[mi][ni][2] + b0, acc[mi][ni][3] + b1);
            *(float2*)(C + (long)rbase * N + cc)       = v0;
            *(float2*)(C + (long)(rbase + 8) * N + cc) = v1;
        }
    }
}

// ------- fused scan (CTAs 0..255, exact R13 core) + dec_W cvt (256..295) ----
// Scan: 4 independent sync groups of 64 CTAs; group bg = cb>>6 owns 8
// batches; single release-reduce counter per group; 2 CTAs/SM. The 40
// converter CTAs fill the remaining co-residency slots (296 = 148*2) and
// stream dec_W -> fp16 under the scan's shadow (scan DRAM use is ~0.5%).
#define SCAN_NB   256
#define CVT_NB    40
#define FUSED_NB  (SCAN_NB + CVT_NB)
#define SCAN_THR  256
#define SCAN_GRP  64
#define HS_PAD    1032

__device__ __forceinline__ void group_barrier(int bg, unsigned gen, int t) {
    __syncthreads();
    if (t == 0) {
        asm volatile("red.release.gpu.global.add.u32 [%0], %1;"
                     :: "l"(&g_arr[bg * 32]), "r"(1u) : "memory");
        unsigned target = gen * (unsigned)SCAN_GRP;
        unsigned v;
        do {
            asm volatile("ld.acquire.gpu.global.u32 %0, [%1];"
                         : "=r"(v) : "l"(&g_arr[bg * 32]) : "memory");
        } while (v < target);
    }
    __syncthreads();
}

__global__ __launch_bounds__(SCAN_THR, 2)
void scan_cvt_kernel(const float* __restrict__ xin,
                     const float* __restrict__ h0,
                     const float* __restrict__ W_hh,
                     const float* __restrict__ b_hh,
                     const float* __restrict__ alpha,
                     float*       __restrict__ hs,
                     __half*      __restrict__ hs16,
                     float*       __restrict__ hidden_f,
                     const float* __restrict__ dec_W)
{
    const int t  = threadIdx.x;
    const int cb = blockIdx.x;

    if (cb >= SCAN_NB) {
        // ---- converter CTAs: dec_W -> fp16, strided over 40 CTAs ----
        const long n4 = (long)NTOKEN * NHID / 4;
        long i = (long)(cb - SCAN_NB) * SCAN_THR + t;
        const long stride = (long)CVT_NB * SCAN_THR;
        for (; i < n4; i += stride) {
            float4 v = ((const float4*)dec_W)[i];
            __half2 h0p = __floats2half2_rn(v.x, v.y);
            __half2 h1p = __floats2half2_rn(v.z, v.w);
            uint2 o = { *(uint32_t*)&h0p, *(uint32_t*)&h1p };
            ((uint2*)g_decW_h)[i] = o;
        }
        return;
    }

    // ---- scan CTAs: exact R13 core ----
    extern __shared__ float sm[];
    float* hsh  = sm;                      // 8 * HS_PAD
    float* red  = sm + 8 * HS_PAD;         // 2048
    float* alph = red + 2048;              // 128

    const int bg = cb >> 6;
    const int jg = cb & 63;
    const int j0 = jg * 16;
    const int b0 = bg * 8;

    const int jj = t & 15;
    const int kg = t >> 4;

    if (t < 128) alph[t] = alpha[t];

    unsigned long long wf[32];
    {
        const float* wrow = W_hh + (long)(j0 + jj) * NHID + kg * 64;
#pragma unroll
        for (int q = 0; q < 16; ++q) {
            ulonglong2 w = *(const ulonglong2*)(wrow + q * 4);
            wf[2 * q]     = w.x;
            wf[2 * q + 1] = w.y;
        }
    }

    const int rb  = t >> 4;
    const int rjj = t & 15;
    const float bh = b_hh[j0 + rjj];

    __syncthreads();

    for (int s = 0; s < SEQ; ++s) {
        const float* hprev = (s == 0) ? (h0 + (long)b0 * NHID)
                                      : (hs + ((long)(s - 1) * BATCH + b0) * NHID);

        float xv = 0.0f;
        long widx = 0;
        if (t < 128) {
            widx = ((long)s * BATCH + b0 + rb) * NHID + j0 + rjj;
            xv = xin[widx];
        }

#pragma unroll
        for (int i = 0; i < 8; ++i) {
            int idx = t + i * SCAN_THR;
            int row = idx >> 8;
            int c4  = idx & 255;
            float4 v = *(const float4*)(hprev + (long)row * NHID + c4 * 4);
            *(float4*)&hsh[row * HS_PAD + c4 * 4] = v;
        }
        __syncthreads();

#pragma unroll
        for (int b = 0; b < 8; ++b) {
            const float* hb = &hsh[b * HS_PAD + kg * 64];
            unsigned long long a0 = 0ull, a1 = 0ull;
#pragma unroll
            for (int q = 0; q < 16; ++q) {
                ulonglong2 hq = *(const ulonglong2*)(hb + q * 4);
                FMA_X2(a0, hq.x, wf[2 * q]);
                FMA_X2(a1, hq.y, wf[2 * q + 1]);
            }
            float2 f0, f1;
            memcpy(&f0, &a0, 8);
            memcpy(&f1, &a1, 8);
            red[(kg * 8 + b) * 16 + jj] = (f0.x + f0.y) + (f1.x + f1.y);
        }
        __syncthreads();

        if (t < 128) {
            float sum = 0.0f;
#pragma unroll
            for (int kk = 0; kk < 16; ++kk) sum += red[(kk * 8 + rb) * 16 + rjj];
            float val = xv + sum + bh;
            float hnew = alph[s] * tanhf(val);
            hs[widx] = hnew;
            hs16[widx] = __float2half_rn(hnew);
            if (s == SEQ - 1) hidden_f[(long)(b0 + rb) * NHID + j0 + rjj] = hnew;
        }

        if (s < SEQ - 1) group_barrier(bg, (unsigned)(s + 1), t);
    }
}

// ---------------- launch ----------------
extern "C" void kernel_launch(void* const* d_in, const int* in_sizes, int n_in,
                              void* d_out, int out_size)
{
    const int*   input  = (const int*)  d_in[0];
    const float* hidden = (const float*)d_in[1];
    const float* emb_W  = (const float*)d_in[2];
    const float* W_ih   = (const float*)d_in[3];
    const float* W_hh   = (const float*)d_in[4];
    const float* b_ih   = (const float*)d_in[5];
    const float* b_hh   = (const float*)d_in[6];
    const float* alpha  = (const float*)d_in[7];
    const float* dec_W  = (const float*)d_in[8];
    const float* dec_b  = (const float*)d_in[9];

    float* decoded  = (float*)d_out;                          // [S,B,NTOKEN]
    float* hidden_f = (float*)d_out + (long)MROWS * NTOKEN;   // [B,NHID]

    void *xin_p, *hs_p, *h16_p, *decwh_p, *wihh_p;
    cudaGetSymbolAddress(&xin_p,   g_xin);
    cudaGetSymbolAddress(&hs_p,    g_hs);
    cudaGetSymbolAddress(&h16_p,   g_h16buf);
    cudaGetSymbolAddress(&decwh_p, g_decW_h);
    cudaGetSymbolAddress(&wihh_p,  g_wih_h);
    float*  xin    = (float*)xin_p;
    float*  hs     = (float*)hs_p;
    __half* h16    = (__half*)h16_p;    // emb16 first, hs16 later
    __half* decwh  = (__half*)decwh_p;
    __half* wihh   = (__half*)wihh_p;

    const int scan_smem = (8 * HS_PAD + 2048 + 128) * (int)sizeof(float);
    cudaFuncSetAttribute(scan_cvt_kernel, cudaFuncAttributeMaxDynamicSharedMemorySize, scan_smem);
    cudaFuncSetAttribute(gemm_f16_ldsm, cudaFuncAttributeMaxDynamicSharedMemorySize, DEC_SMEM);

    // 1) prep_b: W_ih cvt + emb gather (fp16) + counter reset
    prep_b_kernel<<<PREP_B_BLOCKS, 256>>>(W_ih, emb_W, input);

    // 2) xin = emb @ W_ih^T + b_ih on fp16 tensor cores [4096 x 1024]
    gemm_f16_ldsm<<<dim3(MROWS / DBM, NHID / DBN), NTHR, DEC_SMEM>>>(
        h16, wihh, b_ih, xin, MROWS, NHID, NINP);

    // 3) recurrence + concurrent dec_W->fp16 conversion (fills idle DRAM BW)
    scan_cvt_kernel<<<FUSED_NB, SCAN_THR, scan_smem>>>(
        xin, hidden, W_hh, b_hh, alpha, hs, h16, hidden_f, dec_W);

    // 4) decoder: decoded = hs @ dec_W^T + dec_b  [4096 x 32000]  (ncu target)
    gemm_f16_ldsm<<<dim3(MROWS / DBM, NTOKEN / DBN), NTHR, DEC_SMEM>>>(
        h16, decwh, dec_b, decoded, MROWS, NTOKEN, NHID);
}

// round 16
// speedup vs baseline: 1.2108x; 1.1089x over previous
#include <cuda_runtime.h>
#include <cuda_bf16.h>
#include <cuda_fp16.h>
#include <math.h>
#include <stdint.h>
#include <string.h>

// Problem constants
#define SEQ    128
#define BATCH  32
#define NTOKEN 32000
#define NINP   1024
#define NHID   1024
#define MROWS  (SEQ * BATCH)          // 4096

// ---------------- scratch (no runtime allocation allowed) ----------------
__device__ float  g_xin[MROWS * NHID];        // 16 MB
__device__ float  g_hs [MROWS * NHID];        // 16 MB (fp32, scan-internal)
__device__ __half g_h16buf[MROWS * NHID];     // 8 MB (fp16: emb16 then hs16)
__device__ __half g_decW_h[NTOKEN * NHID];    // 64 MB (fp16)
__device__ __half g_wih_h[NHID * NINP];       // 2 MB (fp16)
__device__ unsigned g_arr[8 * 32];            // counters, 128B apart:
// g_arr[0]   scan group 0 progress
// g_arr[32]  scan group 1 progress
// g_arr[128] decoder tile ticket
// g_arr[160] dec_W conversion done count

// ---------------- helpers ----------------
__device__ __forceinline__ uint32_t smem_u32(const void* p) {
    return (uint32_t)__cvta_generic_to_shared(p);
}

#define LDSM_X4(r0, r1, r2, r3, addr) \
    asm volatile("ldmatrix.sync.aligned.m8n8.x4.shared.b16 {%0,%1,%2,%3}, [%4];" \
        : "=r"(r0), "=r"(r1), "=r"(r2), "=r"(r3) : "r"(addr))

#define FMA_X2(acc, a, b) \
    asm volatile("fma.rn.f32x2 %0, %1, %2, %0;" : "+l"(acc) : "l"(a), "l"(b))

#define MMA_F16(acc, a, b) \
    asm volatile( \
        "mma.sync.aligned.m16n8k16.row.col.f32.f16.f16.f32 " \
        "{%0,%1,%2,%3}, {%4,%5,%6,%7}, {%8,%9}, {%0,%1,%2,%3};\n" \
        : "+f"((acc)[0]), "+f"((acc)[1]), "+f"((acc)[2]), "+f"((acc)[3]) \
        : "r"((a)[0]), "r"((a)[1]), "r"((a)[2]), "r"((a)[3]), \
          "r"((b)[0]), "r"((b)[1]))

// =============== prep_b: W_ih cvt + emb gather + counter reset =============
#define PREP_B_BLOCKS 192

__global__ __launch_bounds__(256)
void prep_b_kernel(const float* __restrict__ W_ih,
                   const float* __restrict__ emb_W,
                   const int*   __restrict__ input)
{
    const int bid = blockIdx.x;
    const int t   = threadIdx.x;
    if (bid == 0 && t < 256) g_arr[t] = 0u;

    if (bid < 64) {
        const long n4 = (long)NHID * NINP / 4;
        long i = (long)bid * 256 + t;
        const long stride = 64L * 256;
        for (; i < n4; i += stride) {
            float4 v = ((const float4*)W_ih)[i];
            __half2 h0 = __floats2half2_rn(v.x, v.y);
            __half2 h1 = __floats2half2_rn(v.z, v.w);
            uint2 o = { *(uint32_t*)&h0, *(uint32_t*)&h1 };
            ((uint2*)g_wih_h)[i] = o;
        }
    } else {
        const long n4 = (long)MROWS * NINP / 4;
        long i = (long)(bid - 64) * 256 + t;
        const long stride = 128L * 256;
        for (; i < n4; i += stride) {
            int row = (int)(i >> 8);
            int c4  = (int)(i & 255);
            int tok = input[row];
            float4 v = *(const float4*)(emb_W + (long)tok * NINP + c4 * 4);
            __half2 h0 = __floats2half2_rn(v.x, v.y);
            __half2 h1 = __floats2half2_rn(v.z, v.w);
            uint2 o = { *(uint32_t*)&h0, *(uint32_t*)&h1 };
            *(uint2*)(g_h16buf + (long)row * NINP + c4 * 4) = o;
        }
    }
}

// ============ fp16 GEMM, 128 threads (R13 config) — used for xin only =======
#define DBM 128
#define DBN 128
#define DBK 64
#define NSTG 3
#define NTHR 128
#define A_ST (DBM * 128)         // 16 KB
#define B_ST (DBN * 128)         // 16 KB
#define DEC_SMEM (NSTG * (A_ST + B_ST))   // 96 KB

__global__ __launch_bounds__(NTHR, 2)
void gemm_f16_ldsm(const __half* __restrict__ A,
                   const __half* __restrict__ B,
                   const float*  __restrict__ bias,
                   float*        __restrict__ C,
                   int M, int N, int K)
{
    extern __shared__ __align__(1024) char smem[];
    const uint32_t sA = smem_u32(smem);
    const uint32_t sB = sA + NSTG * A_ST;

    const int t    = threadIdx.x;
    const int warp = t >> 5;
    const int lane = t & 31;
    const int m0   = blockIdx.x * DBM;
    const int n0   = blockIdx.y * DBN;
    const int wm   = warp & 1;
    const int wn   = warp >> 1;
    const int g    = lane >> 2;
    const int tg   = lane & 3;
    const int mat  = lane >> 3;
    const int sub  = lane & 7;

    uint32_t aRowOff[4], aSw[4];
#pragma unroll
    for (int mi = 0; mi < 4; ++mi) {
        int r = wm * 64 + mi * 16 + (mat & 1) * 8 + sub;
        aRowOff[mi] = (uint32_t)(r * 128);
        aSw[mi]     = (uint32_t)(r & 7);
    }
    const uint32_t aMatK = (uint32_t)(mat >> 1);

    uint32_t bRowOff[4], bSw[4];
#pragma unroll
    for (int p = 0; p < 4; ++p) {
        int r = wn * 64 + (p * 2 + (mat >> 1)) * 8 + sub;
        bRowOff[p] = (uint32_t)(r * 128);
        bSw[p]     = (uint32_t)(r & 7);
    }
    const uint32_t bMatK = (uint32_t)(mat & 1);

    float acc[4][8][4];
#pragma unroll
    for (int mi = 0; mi < 4; ++mi)
#pragma unroll
        for (int ni = 0; ni < 8; ++ni)
#pragma unroll
            for (int r = 0; r < 4; ++r) acc[mi][ni][r] = 0.0f;

    auto load_chunk = [&](int c) {
        const int s  = c % NSTG;
        const int k0 = c * DBK;
#pragma unroll
        for (int i = 0; i < 8; ++i) {
            int id  = t + i * NTHR;
            int row = id >> 3;
            int kc  = id & 7;
            uint32_t sw = (uint32_t)(row * 128 + ((kc ^ (row & 7)) << 4));
            asm volatile("cp.async.cg.shared.global [%0], [%1], 16;"
                :: "r"(sA + s * A_ST + sw), "l"(A + (long)(m0 + row) * K + k0 + kc * 8));
        }
#pragma unroll
        for (int i = 0; i < 8; ++i) {
            int id  = t + i * NTHR;
            int row = id >> 3;
            int kc  = id & 7;
            uint32_t sw = (uint32_t)(row * 128 + ((kc ^ (row & 7)) << 4));
            asm volatile("cp.async.cg.shared.global [%0], [%1], 16;"
                :: "r"(sB + s * B_ST + sw), "l"(B + (long)(n0 + row) * K + k0 + kc * 8));
        }
        asm volatile("cp.async.commit_group;");
    };

    const int NCHUNK = K / DBK;
    load_chunk(0);
    load_chunk(1);

    for (int c = 0; c < NCHUNK; ++c) {
        const int buf = c % NSTG;
        asm volatile("cp.async.wait_group 1;");
        __syncthreads();

        if (c + 2 < NCHUNK) load_chunk(c + 2);
        else asm volatile("cp.async.commit_group;");

        const uint32_t Ab = sA + buf * A_ST;
        const uint32_t Bb = sB + buf * B_ST;

#pragma unroll
        for (int kk = 0; kk < 4; ++kk) {
            uint32_t a[4][4];
            uint32_t b[8][2];
            const uint32_t cA = (uint32_t)(kk * 2) + aMatK;
            const uint32_t cB = (uint32_t)(kk * 2) + bMatK;
#pragma unroll
            for (int mi = 0; mi < 4; ++mi)
                LDSM_X4(a[mi][0], a[mi][1], a[mi][2], a[mi][3],
                        Ab + aRowOff[mi] + (((cA ^ aSw[mi])) << 4));
#pragma unroll
            for (int p = 0; p < 4; ++p) {
                uint32_t r0, r1, r2, r3;
                LDSM_X4(r0, r1, r2, r3, Bb + bRowOff[p] + (((cB ^ bSw[p])) << 4));
                b[2 * p][0] = r0;     b[2 * p][1] = r1;
                b[2 * p + 1][0] = r2; b[2 * p + 1][1] = r3;
            }
#pragma unroll
            for (int mi = 0; mi < 4; ++mi)
#pragma unroll
                for (int ni = 0; ni < 8; ++ni)
                    MMA_F16(acc[mi][ni], a[mi], b[ni]);
        }
    }

#pragma unroll
    for (int mi = 0; mi < 4; ++mi) {
        int rbase = m0 + wm * 64 + mi * 16 + g;
#pragma unroll
        for (int ni = 0; ni < 8; ++ni) {
            int cc = n0 + wn * 64 + ni * 8 + 2 * tg;
            float b0 = bias[cc], b1 = bias[cc + 1];
            float2 v0 = make_float2(acc[mi][ni][0] + b0, acc[mi][ni][1] + b1);
            float2 v1 = make_float2(acc[mi][ni][2] + b0, acc[mi][ni][3] + b1);
            *(float2*)(C + (long)rbase * N + cc)       = v0;
            *(float2*)(C + (long)(rbase + 8) * N + cc) = v1;
        }
    }
}

// ================= FUSED scan + dec_W cvt + decoder =================
// 296 CTAs x 256 threads, 96KB+128 smem, 2 CTAs/SM (all co-resident).
// CTAs 0..127  : scan (2 groups x 64 CTAs; group bg owns 16 batches; CTA
//                covers 16 cols; W in regs; h broadcast-LDS). Publishes
//                progress every step via g_arr[bg*32]. Then joins decoder.
// CTAs 128..295: convert dec_W -> fp16 (168-way strided), arrive cvt
//                counter, then pull decoder tiles from the ticket counter.
// Decoder tile tk: mt = tk/250 (row block, needs scan steps <= 4mt+3),
// nt = tk%250. Progress gate: both group counters >= 64*(4mt+4); acquire
// semantics make hs16 visible.
#define FUSED_NB   296
#define SCAN_CTAS  128
#define CVT_CTAS   168
#define FTHR       256
#define SCAN_GRP   64
#define HS_PAD     1032
#define NTILE_N    250
#define NTILES     (32 * NTILE_N)
#define FUSED_SMEM (DEC_SMEM + 128)

__device__ __forceinline__ unsigned ld_acq(const unsigned* p) {
    unsigned v;
    asm volatile("ld.acquire.gpu.global.u32 %0, [%1];" : "=r"(v) : "l"(p) : "memory");
    return v;
}

__global__ __launch_bounds__(FTHR, 2)
void fused_kernel(const float* __restrict__ xin,
                  const float* __restrict__ h0,
                  const float* __restrict__ W_hh,
                  const float* __restrict__ b_hh,
                  const float* __restrict__ alpha,
                  float*       __restrict__ hs,
                  __half*      __restrict__ hs16,
                  float*       __restrict__ hidden_f,
                  const float* __restrict__ dec_W,
                  const __half* __restrict__ decW_h_c,
                  const float* __restrict__ dec_b,
                  float*       __restrict__ decoded)
{
    extern __shared__ __align__(1024) char smem[];
    const int t  = threadIdx.x;
    const int cb = blockIdx.x;

    if (cb < SCAN_CTAS) {
        // ================= scan =================
        float* sm   = (float*)smem;
        float* hsh  = sm;                       // 16 * HS_PAD
        float* red  = sm + 16 * HS_PAD;         // 16*16*16 = 4096
        float* alph = red + 4096;               // 128

        const int bg = cb >> 6;        // 0,1 : batch group (16 batches)
        const int jg = cb & 63;        // col group (16 cols)
        const int j0 = jg * 16;
        const int b0 = bg * 16;

        const int jj = t & 15;
        const int kg = t >> 4;         // 0..15, K range [kg*64, +64)

        if (t < 128) alph[t] = alpha[t];

        unsigned long long wf[32];
        {
            const float* wrow = W_hh + (long)(j0 + jj) * NHID + kg * 64;
#pragma unroll
            for (int q = 0; q < 16; ++q) {
                ulonglong2 w = *(const ulonglong2*)(wrow + q * 4);
                wf[2 * q]     = w.x;
                wf[2 * q + 1] = w.y;
            }
        }

        const int rb  = t >> 4;        // batch 0..15
        const int rjj = t & 15;        // col
        const float bh = b_hh[j0 + rjj];

        __syncthreads();

        for (int s = 0; s < SEQ; ++s) {
            const float* hprev = (s == 0) ? (h0 + (long)b0 * NHID)
                                          : (hs + ((long)(s - 1) * BATCH + b0) * NHID);

            float xv;
            long widx = ((long)s * BATCH + b0 + rb) * NHID + j0 + rjj;
            xv = xin[widx];

            // stage 16 rows of h (coalesced, 16 float4/thread)
#pragma unroll
            for (int i = 0; i < 16; ++i) {
                int idx = t + i * FTHR;        // 0..4095 float4
                int row = idx >> 8;
                int c4  = idx & 255;
                float4 v = *(const float4*)(hprev + (long)row * NHID + c4 * 4);
                *(float4*)&hsh[row * HS_PAD + c4 * 4] = v;
            }
            __syncthreads();

#pragma unroll
            for (int b = 0; b < 16; ++b) {
                const float* hb = &hsh[b * HS_PAD + kg * 64];
                unsigned long long a0 = 0ull, a1 = 0ull;
#pragma unroll
                for (int q = 0; q < 16; ++q) {
                    ulonglong2 hq = *(const ulonglong2*)(hb + q * 4);
                    FMA_X2(a0, hq.x, wf[2 * q]);
                    FMA_X2(a1, hq.y, wf[2 * q + 1]);
                }
                float2 f0, f1;
                memcpy(&f0, &a0, 8);
                memcpy(&f1, &a1, 8);
                red[(kg * 16 + b) * 16 + jj] = (f0.x + f0.y) + (f1.x + f1.y);
            }
            __syncthreads();

            {
                float sum = 0.0f;
#pragma unroll
                for (int kk = 0; kk < 16; ++kk) sum += red[(kk * 16 + rb) * 16 + rjj];
                float val = xv + sum + bh;
                float hnew = alph[s] * tanhf(val);
                hs[widx] = hnew;
                hs16[widx] = __float2half_rn(hnew);
                if (s == SEQ - 1) hidden_f[(long)(b0 + rb) * NHID + j0 + rjj] = hnew;
            }

            __syncthreads();   // all writes of this CTA done
            if (t == 0) {
                asm volatile("red.release.gpu.global.add.u32 [%0], %1;"
                             :: "l"(&g_arr[bg * 32]), "r"(1u) : "memory");
                if (s < SEQ - 1) {
                    unsigned target = (unsigned)(s + 1) * (unsigned)SCAN_GRP;
                    while (ld_acq(&g_arr[bg * 32]) < target) { }
                }
            }
            __syncthreads();
        }
        // fall through: join the decoder pool
    } else {
        // ============== dec_W -> fp16 conversion ==============
        const long n4 = (long)NTOKEN * NHID / 4;
        long i = (long)(cb - SCAN_CTAS) * FTHR + t;
        const long stride = (long)CVT_CTAS * FTHR;
        for (; i < n4; i += stride) {
            float4 v = ((const float4*)dec_W)[i];
            __half2 h0p = __floats2half2_rn(v.x, v.y);
            __half2 h1p = __floats2half2_rn(v.z, v.w);
            uint2 o = { *(uint32_t*)&h0p, *(uint32_t*)&h1p };
            ((uint2*)g_decW_h)[i] = o;
        }
        __syncthreads();
        if (t == 0) {
            asm volatile("red.release.gpu.global.add.u32 [%0], %1;"
                         :: "l"(&g_arr[160]), "r"(1u) : "memory");
        }
    }

    // ================= decoder worker =================
    // wait for conversion complete
    if (t == 0) {
        while (ld_acq(&g_arr[160]) < (unsigned)CVT_CTAS) { }
    }
    __syncthreads();

    const uint32_t sA = smem_u32(smem);
    const uint32_t sB = sA + NSTG * A_ST;
    unsigned* ctrl = (unsigned*)(smem + DEC_SMEM);

    const int warp = t >> 5;          // 0..7
    const int lane = t & 31;
    const int wm   = warp & 1;        // 2 m-subtiles of 64
    const int wn   = warp >> 1;       // 4 n-subtiles of 32
    const int g    = lane >> 2;
    const int tg   = lane & 3;
    const int mat  = lane >> 3;
    const int sub  = lane & 7;

    uint32_t aRowOff[4], aSw[4];
#pragma unroll
    for (int mi = 0; mi < 4; ++mi) {
        int r = wm * 64 + mi * 16 + (mat & 1) * 8 + sub;
        aRowOff[mi] = (uint32_t)(r * 128);
        aSw[mi]     = (uint32_t)(r & 7);
    }
    const uint32_t aMatK = (uint32_t)(mat >> 1);

    uint32_t bRowOff[2], bSw[2];
#pragma unroll
    for (int p = 0; p < 2; ++p) {
        int r = wn * 32 + (p * 2 + (mat >> 1)) * 8 + sub;
        bRowOff[p] = (uint32_t)(r * 128);
        bSw[p]     = (uint32_t)(r & 7);
    }
    const uint32_t bMatK = (uint32_t)(mat & 1);

    for (;;) {
        if (t == 0) {
            unsigned tk;
            asm volatile("atom.add.release.gpu.global.u32 %0, [%1], %2;"
                         : "=r"(tk) : "l"(&g_arr[128]), "r"(1u) : "memory");
            ctrl[0] = tk;
            if (tk < (unsigned)NTILES) {
                int mt = (int)(tk / NTILE_N);
                unsigned target = 64u * (unsigned)(4 * mt + 4);
                while (ld_acq(&g_arr[0]) < target || ld_acq(&g_arr[32]) < target) { }
            }
        }
        __syncthreads();
        unsigned tk = ctrl[0];
        if (tk >= (unsigned)NTILES) break;
        const int m0 = (int)(tk / NTILE_N) * 128;
        const int n0 = (int)(tk % NTILE_N) * 128;

        float acc[4][4][4];
#pragma unroll
        for (int mi = 0; mi < 4; ++mi)
#pragma unroll
            for (int ni = 0; ni < 4; ++ni)
#pragma unroll
                for (int r = 0; r < 4; ++r) acc[mi][ni][r] = 0.0f;

        auto load_chunk = [&](int c) {
            const int s  = c % NSTG;
            const int k0 = c * DBK;
#pragma unroll
            for (int i = 0; i < 4; ++i) {
                int id  = t + i * FTHR;
                int row = id >> 3;
                int kc  = id & 7;
                uint32_t sw = (uint32_t)(row * 128 + ((kc ^ (row & 7)) << 4));
                asm volatile("cp.async.cg.shared.global [%0], [%1], 16;"
                    :: "r"(sA + s * A_ST + sw),
                       "l"(hs16 + (long)(m0 + row) * NHID + k0 + kc * 8));
            }
#pragma unroll
            for (int i = 0; i < 4; ++i) {
                int id  = t + i * FTHR;
                int row = id >> 3;
                int kc  = id & 7;
                uint32_t sw = (uint32_t)(row * 128 + ((kc ^ (row & 7)) << 4));
                asm volatile("cp.async.cg.shared.global [%0], [%1], 16;"
                    :: "r"(sB + s * B_ST + sw),
                       "l"(decW_h_c + (long)(n0 + row) * NHID + k0 + kc * 8));
            }
            asm volatile("cp.async.commit_group;");
        };

        const int NCHUNK = NHID / DBK;   // 16
        load_chunk(0);
        load_chunk(1);

        for (int c = 0; c < NCHUNK; ++c) {
            const int buf = c % NSTG;
            asm volatile("cp.async.wait_group 1;");
            __syncthreads();

            if (c + 2 < NCHUNK) load_chunk(c + 2);
            else asm volatile("cp.async.commit_group;");

            const uint32_t Ab = sA + buf * A_ST;
            const uint32_t Bb = sB + buf * B_ST;

#pragma unroll
            for (int kk = 0; kk < 4; ++kk) {
                uint32_t a[4][4];
                uint32_t b[4][2];
                const uint32_t cA = (uint32_t)(kk * 2) + aMatK;
                const uint32_t cB = (uint32_t)(kk * 2) + bMatK;
#pragma unroll
                for (int mi = 0; mi < 4; ++mi)
                    LDSM_X4(a[mi][0], a[mi][1], a[mi][2], a[mi][3],
                            Ab + aRowOff[mi] + (((cA ^ aSw[mi])) << 4));
#pragma unroll
                for (int p = 0; p < 2; ++p) {
                    uint32_t r0, r1, r2, r3;
                    LDSM_X4(r0, r1, r2, r3, Bb + bRowOff[p] + (((cB ^ bSw[p])) << 4));
                    b[2 * p][0] = r0;     b[2 * p][1] = r1;
                    b[2 * p + 1][0] = r2; b[2 * p + 1][1] = r3;
                }
#pragma unroll
                for (int mi = 0; mi < 4; ++mi)
#pragma unroll
                    for (int ni = 0; ni < 4; ++ni)
                        MMA_F16(acc[mi][ni], a[mi], b[ni]);
            }
            __syncthreads();
        }

        // epilogue
#pragma unroll
        for (int mi = 0; mi < 4; ++mi) {
            int rbase = m0 + wm * 64 + mi * 16 + g;
#pragma unroll
            for (int ni = 0; ni < 4; ++ni) {
                int cc = n0 + wn * 32 + ni * 8 + 2 * tg;
                float b0 = dec_b[cc], b1 = dec_b[cc + 1];
                float2 v0 = make_float2(acc[mi][ni][0] + b0, acc[mi][ni][1] + b1);
                float2 v1 = make_float2(acc[mi][ni][2] + b0, acc[mi][ni][3] + b1);
                *(float2*)(decoded + (long)rbase * NTOKEN + cc)       = v0;
                *(float2*)(decoded + (long)(rbase + 8) * NTOKEN + cc) = v1;
            }
        }
    }
}

// ---------------- launch ----------------
extern "C" void kernel_launch(void* const* d_in, const int* in_sizes, int n_in,
                              void* d_out, int out_size)
{
    const int*   input  = (const int*)  d_in[0];
    const float* hidden = (const float*)d_in[1];
    const float* emb_W  = (const float*)d_in[2];
    const float* W_ih   = (const float*)d_in[3];
    const float* W_hh   = (const float*)d_in[4];
    const float* b_ih   = (const float*)d_in[5];
    const float* b_hh   = (const float*)d_in[6];
    const float* alpha  = (const float*)d_in[7];
    const float* dec_W  = (const float*)d_in[8];
    const float* dec_b  = (const float*)d_in[9];

    float* decoded  = (float*)d_out;                          // [S,B,NTOKEN]
    float* hidden_f = (float*)d_out + (long)MROWS * NTOKEN;   // [B,NHID]

    void *xin_p, *hs_p, *h16_p, *decwh_p, *wihh_p;
    cudaGetSymbolAddress(&xin_p,   g_xin);
    cudaGetSymbolAddress(&hs_p,    g_hs);
    cudaGetSymbolAddress(&h16_p,   g_h16buf);
    cudaGetSymbolAddress(&decwh_p, g_decW_h);
    cudaGetSymbolAddress(&wihh_p,  g_wih_h);
    float*  xin    = (float*)xin_p;
    float*  hs     = (float*)hs_p;
    __half* h16    = (__half*)h16_p;    // emb16 first, hs16 later
    __half* decwh  = (__half*)decwh_p;
    __half* wihh   = (__half*)wihh_p;

    cudaFuncSetAttribute(gemm_f16_ldsm, cudaFuncAttributeMaxDynamicSharedMemorySize, DEC_SMEM);
    cudaFuncSetAttribute(fused_kernel, cudaFuncAttributeMaxDynamicSharedMemorySize, FUSED_SMEM);

    // 1) prep_b: W_ih cvt + emb gather (fp16) + counter reset
    prep_b_kernel<<<PREP_B_BLOCKS, 256>>>(W_ih, emb_W, input);

    // 2) xin = emb @ W_ih^T + b_ih on fp16 tensor cores [4096 x 1024]
    gemm_f16_ldsm<<<dim3(MROWS / DBM, NHID / DBN), NTHR, DEC_SMEM>>>(
        h16, wihh, b_ih, xin, MROWS, NHID, NINP);

    // 3) fused: scan (progress-published) + dec_W cvt + overlapped decoder
    fused_kernel<<<FUSED_NB, FTHR, FUSED_SMEM>>>(
        xin, hidden, W_hh, b_hh, alpha, hs, h16, hidden_f,
        dec_W, decwh, dec_b, decoded);
}